// round 16
// baseline (speedup 1.0000x reference)
#include <cuda_runtime.h>
#include <cstdint>

#define HID   64
#define NVEC  16384
#define NB    8192

// bot/top (s-product + eta*(h@W2+b2)): g_bt[n][k], k<8192 bot, >=8192 top
__device__ float g_bt[128 * NVEC];   // 8 MB
__device__ int   g_flags[128];       // [group*16 + slab] doorbells

// ---- packed fp32x2 helpers ----
__device__ __forceinline__ unsigned long long pack2(float x, float y) {
    unsigned long long d;
    asm("mov.b64 %0, {%1, %2};" : "=l"(d) : "f"(x), "f"(y));
    return d;
}
__device__ __forceinline__ void unpack2(unsigned long long d, float& x, float& y) {
    asm("mov.b64 {%0, %1}, %2;" : "=f"(x), "=f"(y) : "l"(d));
}
__device__ __forceinline__ unsigned long long fma2(unsigned long long a,
                                                   unsigned long long b,
                                                   unsigned long long c) {
    unsigned long long d;
    asm("fma.rn.f32x2 %0, %1, %2, %3;" : "=l"(d) : "l"(a), "l"(b), "l"(c));
    return d;
}

__device__ __forceinline__ void cp_async16(uint32_t dst, const void* src) {
    asm volatile("cp.async.cg.shared.global [%0], [%1], 16;" :: "r"(dst), "l"(src));
}
#define COMMIT() asm volatile("cp.async.commit_group;")
#define WAITG(N) asm volatile("cp.async.wait_group " #N ";")

__global__ void reset_flags()
{
    if (threadIdx.x < 128) g_flags[threadIdx.x] = 0;
}

// ---------------------------------------------------------------------------
// Fused kernel: 128 blocks x 512 threads, all resident (1 wave).
// Phase A (block b): slab = b>>3 (0..15), group g = b&7 -> computes bt for
//   16 samples of group g on its 1024-k slab, then releases flag[g*16+slab].
// Phase B (block b): sample n = b; polls per-tile flag pairs of group n>>4,
//   streams tiles via cp.async (2-tile lookahead), runs the FFMA2 scan.
// Dynamic smem (union):
//   Phase A: sh_s[8192 f] | sh_hd[1024 u64]            (40 KB)
//   Phase B: buf[8][2048 f] | sh_t[1024 f] | vd[512 u64] (72 KB)
// ---------------------------------------------------------------------------
#define SMEM_FLOATS (16384 + 1024 + 1024)

__global__ void __launch_bounds__(512) fused_all(
    const int*   __restrict__ cfg,
    const float* __restrict__ A,
    const float* __restrict__ W1,
    const float* __restrict__ b1,
    const float* __restrict__ W2,
    const float* __restrict__ b2,
    float*       __restrict__ out)
{
    extern __shared__ float sm[];
    __shared__ unsigned sh_mask[16];

    const int tid = threadIdx.x;
    const int b   = blockIdx.x;

    // =========================== PHASE A ===============================
    {
        float* sh_s = sm;                                        // 8192 floats
        unsigned long long* sh_hd = (unsigned long long*)(sm + 8192);  // 1024 u64

        const int slab   = b >> 3;          // 0..15
        const int g      = b & 7;
        const int n0     = g * 16;
        const int xx     = slab & 7;
        const int isTop  = slab >> 3;
        const int ybase  = isTop * 2;       // bot: y=0,1 ; top: y=2,3
        const int shalf  = tid >> 8;        // 8-sample half
        const int tk     = tid & 255;
        const int k4     = slab * 1024 + tk * 4;
        const int sbase  = shalf * 8;

        // cfg bitmasks (cfg in {0,1})
        if (tid < 16) {
            const int* crow = cfg + (n0 + tid) * 32;
            unsigned m = 0;
            #pragma unroll
            for (int i = 0; i < 32; i++) m |= ((unsigned)crow[i] & 1u) << i;
            sh_mask[tid] = m;
        }
        __syncthreads();

        // Gather the two needed A-slices per sample (8192 floats, 16/thread)
        const float2* A2 = (const float2*)A;
        #pragma unroll
        for (int q = 0; q < 16; q++) {
            const int m   = q * 512 + tid;
            const int s   = m >> 9;
            const int sl  = (m >> 8) & 1;
            const int idx = m & 255;
            const float2 a = A2[(xx * 4 + ybase + sl) * 256 + idx];
            const int bit = xx * 4 + ybase + sl;
            sh_s[m] = ((sh_mask[s] >> bit) & 1u) ? a.y : a.x;
        }

        // H = relu(cfg@W1+b1) via predicated adds (exact), duplicated {h,h}
        {
            const int o  = tid & 63;
            const int sq = tid >> 6;            // 0..7 -> samples sq, sq+8
            const unsigned m0 = sh_mask[sq];
            const unsigned m1 = sh_mask[sq + 8];
            const float bb = b1[o];
            float a0 = bb, a1 = bb;
            #pragma unroll
            for (int i = 0; i < 32; i++) {
                const float wv = W1[i * HID + o];
                if ((m0 >> i) & 1u) a0 += wv;
                if ((m1 >> i) & 1u) a1 += wv;
            }
            a0 = fmaxf(a0, 0.f); a1 = fmaxf(a1, 0.f);
            sh_hd[sq * HID + o]       = pack2(a0, a0);
            sh_hd[(sq + 8) * HID + o] = pack2(a1, a1);
        }
        __syncthreads();

        // GEMM: acc[s*2+p], 8 samples x 2 k-pairs per thread
        unsigned long long acc[16];
        #pragma unroll
        for (int q = 0; q < 16; q++) acc[q] = 0ull;

        #pragma unroll 4
        for (int jq = 0; jq < 16; jq++) {
            const int j0 = jq * 4;
            const float4 w0 = *(const float4*)(W2 + (j0 + 0) * NVEC + k4);
            const float4 w1 = *(const float4*)(W2 + (j0 + 1) * NVEC + k4);
            const float4 w2 = *(const float4*)(W2 + (j0 + 2) * NVEC + k4);
            const float4 w3 = *(const float4*)(W2 + (j0 + 3) * NVEC + k4);
            const unsigned long long w0lo = pack2(w0.x, w0.y), w0hi = pack2(w0.z, w0.w);
            const unsigned long long w1lo = pack2(w1.x, w1.y), w1hi = pack2(w1.z, w1.w);
            const unsigned long long w2lo = pack2(w2.x, w2.y), w2hi = pack2(w2.z, w2.w);
            const unsigned long long w3lo = pack2(w3.x, w3.y), w3hi = pack2(w3.z, w3.w);

            #pragma unroll
            for (int s = 0; s < 8; s++) {
                const int sn = sbase + s;
                const ulonglong2 hd01 = *(const ulonglong2*)(sh_hd + sn * HID + j0);
                const ulonglong2 hd23 = *(const ulonglong2*)(sh_hd + sn * HID + j0 + 2);
                unsigned long long a0 = acc[s * 2 + 0];
                unsigned long long a1 = acc[s * 2 + 1];
                a0 = fma2(hd01.x, w0lo, a0);  a1 = fma2(hd01.x, w0hi, a1);
                a0 = fma2(hd01.y, w1lo, a0);  a1 = fma2(hd01.y, w1hi, a1);
                a0 = fma2(hd23.x, w2lo, a0);  a1 = fma2(hd23.x, w2hi, a1);
                a0 = fma2(hd23.y, w3lo, a0);  a1 = fma2(hd23.y, w3hi, a1);
                acc[s * 2 + 0] = a0;
                acc[s * 2 + 1] = a1;
            }
        }

        // Epilogue: add s-product, write bt
        const int idx = tk * 4;
        const int ii = idx >> 6;
        const int jj = (idx >> 2) & 15;
        const int l = ii >> 2, L = ii & 3, r = jj >> 2, R = jj & 3;
        const float4 bk  = *(const float4*)(b2 + k4);
        const float  eta = 0.001f;

        if (!isTop) {
            #pragma unroll
            for (int s = 0; s < 8; s++) {
                const int sn = sbase + s;
                float4 cr;
                unpack2(acc[s * 2 + 0], cr.x, cr.y);
                unpack2(acc[s * 2 + 1], cr.z, cr.w);
                cr.x += bk.x; cr.y += bk.y; cr.z += bk.z; cr.w += bk.w;

                const float* sa = sh_s + sn * 512;
                const float* sb = sh_s + sn * 512 + 256;
                const float4  a0 = *(const float4*)(sa + l * 64 + r * 16);
                const float4* b4 = (const float4*)(sb + L * 64 + R * 16);
                const float4 b0 = b4[0], b1v = b4[1], b2v = b4[2], b3v = b4[3];
                float4 o4;
                o4.x = fmaf(a0.x, b0.x, fmaf(a0.y, b1v.x, fmaf(a0.z, b2v.x, fmaf(a0.w, b3v.x, eta * cr.x))));
                o4.y = fmaf(a0.x, b0.y, fmaf(a0.y, b1v.y, fmaf(a0.z, b2v.y, fmaf(a0.w, b3v.y, eta * cr.y))));
                o4.z = fmaf(a0.x, b0.z, fmaf(a0.y, b1v.z, fmaf(a0.z, b2v.z, fmaf(a0.w, b3v.z, eta * cr.z))));
                o4.w = fmaf(a0.x, b0.w, fmaf(a0.y, b1v.w, fmaf(a0.z, b2v.w, fmaf(a0.w, b3v.w, eta * cr.w))));
                *(float4*)(g_bt + (n0 + sn) * NVEC + k4) = o4;
            }
        } else {
            #pragma unroll
            for (int s = 0; s < 8; s++) {
                const int sn = sbase + s;
                float4 cr;
                unpack2(acc[s * 2 + 0], cr.x, cr.y);
                unpack2(acc[s * 2 + 1], cr.z, cr.w);
                cr.x += bk.x; cr.y += bk.y; cr.z += bk.z; cr.w += bk.w;

                const float* sa = sh_s + sn * 512;
                const float* sb = sh_s + sn * 512 + 256;
                const float4* c4 = (const float4*)(sa + l * 64 + r * 16);
                const float4 c0 = c4[0], c1 = c4[1], c2 = c4[2], c3 = c4[3];
                const float e0 = sb[L * 64 + R * 16 + 0];
                const float e1 = sb[L * 64 + R * 16 + 4];
                const float e2 = sb[L * 64 + R * 16 + 8];
                const float e3 = sb[L * 64 + R * 16 + 12];
                float4 o4;
                o4.x = fmaf(c0.x, e0, fmaf(c0.y, e1, fmaf(c0.z, e2, fmaf(c0.w, e3, eta * cr.x))));
                o4.y = fmaf(c1.x, e0, fmaf(c1.y, e1, fmaf(c1.z, e2, fmaf(c1.w, e3, eta * cr.y))));
                o4.z = fmaf(c2.x, e0, fmaf(c2.y, e1, fmaf(c2.z, e2, fmaf(c2.w, e3, eta * cr.z))));
                o4.w = fmaf(c3.x, e0, fmaf(c3.y, e1, fmaf(c3.z, e2, fmaf(c3.w, e3, eta * cr.w))));
                *(float4*)(g_bt + (n0 + sn) * NVEC + k4) = o4;
            }
        }

        __syncthreads();        // all bt stores of this block issued
        if (tid == 0) {
            __threadfence();    // release bt to gpu scope
            *((volatile int*)&g_flags[g * 16 + slab]) = 1;
        }
        __syncthreads();        // smem safe to reuse
    }

    // =========================== PHASE B ===============================
    {
        float* buf  = sm;                                   // 8 x 2048
        float* sh_t = sm + 16384;
        unsigned long long* sh_vd = (unsigned long long*)(sm + 17408);

        const int n  = b;
        const int gn = n >> 4;
        volatile int* fl = (volatile int*)(g_flags + gn * 16);
        const float* src = g_bt + n * NVEC;

        const int half = tid >> 8;
        const int e4   = (tid & 255) * 4;
        const uint32_t dst0 =
            (uint32_t)__cvta_generic_to_shared(buf + half * 1024 + e4);

        if (tid < 256) {
            const float v = (tid == 0) ? 1.0f : 0.0f;
            sh_vd[tid] = pack2(v, v);
        }

        // lookahead: tiles 0 and 1
        #pragma unroll
        for (int p = 0; p < 2; p++) {
            if (tid == 0) {
                while (fl[p] == 0 || fl[8 + p] == 0) {}
                __threadfence();   // acquire
            }
            __syncthreads();
            cp_async16(dst0 + p * 2048 * 4, src + p * 1024 + half * 8192 + e4);
            COMMIT();
        }

        const int w    = tid >> 5;
        const int lane = tid & 31;
        const int I15  = lane & 15;
        const int ih   = lane >> 4;

        #pragma unroll
        for (int x = 0; x < 8; x++) {
            // issue tile x+2 (one commit group per iteration, empty if none)
            if (x + 2 < 8) {
                if (tid == 0) {
                    while (fl[x + 2] == 0 || fl[8 + x + 2] == 0) {}
                    __threadfence();
                }
                __syncthreads();
                cp_async16(dst0 + (x + 2) * 2048 * 4,
                           src + (x + 2) * 1024 + half * 8192 + e4);
            }
            COMMIT();
            WAITG(2);          // tiles 0..x complete
            __syncthreads();   // cp.async results + prev v visible block-wide

            const float* bt = buf + x * 2048;
            const float* tp = bt + 1024;
            const unsigned long long* vcur  = sh_vd + (x & 1) * 256;
            unsigned long long*       vnext = sh_vd + ((x & 1) ^ 1) * 256;

            // step1: t[I,U] = sum_i v[i,I] * bot[i*64 + w*4 + U]
            {
                unsigned long long a01 = 0ull, a23 = 0ull;
                #pragma unroll
                for (int it = 0; it < 8; it++) {
                    const int i = ih * 8 + it;
                    const ulonglong2 bb = *(const ulonglong2*)(bt + i * 64 + w * 4);
                    const unsigned long long vv = vcur[i * 16 + I15];
                    a01 = fma2(bb.x, vv, a01);
                    a23 = fma2(bb.y, vv, a23);
                }
                float t0, t1, t2, t3;
                unpack2(a01, t0, t1);
                unpack2(a23, t2, t3);
                t0 += __shfl_xor_sync(0xffffffffu, t0, 16);
                t1 += __shfl_xor_sync(0xffffffffu, t1, 16);
                t2 += __shfl_xor_sync(0xffffffffu, t2, 16);
                t3 += __shfl_xor_sync(0xffffffffu, t3, 16);
                if (lane < 16)
                    *(float4*)(sh_t + w * 64 + I15 * 4) = make_float4(t0, t1, t2, t3);
            }
            __syncwarp();

            // step2: v'[w,J] = sum_{I,U} t[I,U] * top[I*64 + J*4 + U]
            {
                unsigned long long c01 = 0ull, c23 = 0ull;
                #pragma unroll
                for (int it = 0; it < 8; it++) {
                    const int I = ih * 8 + it;
                    const ulonglong2 tt = *(const ulonglong2*)(sh_t + w * 64 + I * 4);
                    const ulonglong2 pp = *(const ulonglong2*)(tp + I * 64 + I15 * 4);
                    c01 = fma2(tt.x, pp.x, c01);
                    c23 = fma2(tt.y, pp.y, c23);
                }
                float s0, s1, s2, s3;
                unpack2(c01, s0, s1);
                unpack2(c23, s2, s3);
                float nv = (s0 + s1) + (s2 + s3);
                nv += __shfl_xor_sync(0xffffffffu, nv, 16);
                if (lane < 16) vnext[w * 16 + I15] = pack2(nv, nv);
            }
            __syncthreads();
        }

        if (tid == 0) {
            float a, c;
            unpack2(sh_vd[0], a, c);   // x=7 wrote half 0
            out[n] = a;
        }
    }
}

// ---------------------------------------------------------------------------
extern "C" void kernel_launch(void* const* d_in, const int* in_sizes, int n_in,
                              void* d_out, int out_size)
{
    const int*   cfg = (const int*)  d_in[0];
    const float* A   = (const float*)d_in[1];
    const float* W1  = (const float*)d_in[2];
    const float* b1  = (const float*)d_in[3];
    const float* W2  = (const float*)d_in[4];
    const float* b2  = (const float*)d_in[5];
    float* out = (float*)d_out;

    cudaFuncSetAttribute(fused_all,
                         cudaFuncAttributeMaxDynamicSharedMemorySize,
                         SMEM_FLOATS * 4);

    reset_flags<<<1, 128>>>();
    fused_all<<<128, 512, SMEM_FLOATS * 4>>>(cfg, A, W1, b1, W2, b2, out);
}